// round 15
// baseline (speedup 1.0000x reference)
#include <cuda_runtime.h>
#include <cuda_bf16.h>
#include <cstdint>

// Problem constants
constexpr int N_TOK = 3072;
constexpr int D     = 1280;
constexpr int H     = 16;
constexpr int HK    = 80;     // head dim
constexpr int WPR   = HK / 2; // packed bf16 words per row (40)
constexpr int NSEG  = 8;
constexpr float SCALE = 0.111803398874989485f; // 80^-0.5

// ---------------- scratch ----------------
__device__ uint32_t g_hid_tf[N_TOK * D];        // tf32 of hidden
__device__ uint32_t g_qkvw_tf[D * 3 * D];       // tf32 of qkv_w
__device__ uint32_t g_projw_tf[D * D];          // tf32 of proj_w
__device__ float    g_qkv[N_TOK * 3 * D];       // [N][3][H][K] fp32
__device__ uint32_t g_qhib[H * N_TOK * WPR];    // bf16x2 hi of SCALE*rope(q)
__device__ uint32_t g_qlob[H * N_TOK * WPR];
__device__ uint32_t g_khib[H * N_TOK * WPR];
__device__ uint32_t g_klob[H * N_TOK * WPR];
__device__ uint32_t g_vtf[H * N_TOK * HK];      // tf32 v
__device__ uint32_t g_attn_tf[N_TOK * D];       // tf32 attn out [N][H*K]

// ---------------- helpers ----------------
__device__ __forceinline__ uint32_t f2tf32(float x) {
    uint32_t r;
    asm("cvt.rna.tf32.f32 %0, %1;" : "=r"(r) : "f"(x));
    return r;
}
__device__ __forceinline__ void mma_tf32(float c[4], const uint32_t a[4], const uint32_t b[2]) {
    asm volatile(
        "mma.sync.aligned.m16n8k8.row.col.f32.tf32.tf32.f32 "
        "{%0,%1,%2,%3}, {%4,%5,%6,%7}, {%8,%9}, {%0,%1,%2,%3};"
        : "+f"(c[0]), "+f"(c[1]), "+f"(c[2]), "+f"(c[3])
        : "r"(a[0]), "r"(a[1]), "r"(a[2]), "r"(a[3]), "r"(b[0]), "r"(b[1]));
}
__device__ __forceinline__ void mma_bf16(float c[4], const uint32_t a[4], const uint32_t b[2]) {
    asm volatile(
        "mma.sync.aligned.m16n8k16.row.col.f32.bf16.bf16.f32 "
        "{%0,%1,%2,%3}, {%4,%5,%6,%7}, {%8,%9}, {%0,%1,%2,%3};"
        : "+f"(c[0]), "+f"(c[1]), "+f"(c[2]), "+f"(c[3])
        : "r"(a[0]), "r"(a[1]), "r"(a[2]), "r"(a[3]), "r"(b[0]), "r"(b[1]));
}
__device__ __forceinline__ uint32_t bf16bits(float x) {
    const __nv_bfloat16 b = __float2bfloat16(x);
    return (uint32_t)*reinterpret_cast<const uint16_t*>(&b);
}
__device__ __forceinline__ float bf16val(uint32_t bits) {
    const uint16_t u = (uint16_t)bits;
    return __bfloat162float(*reinterpret_cast<const __nv_bfloat16*>(&u));
}
__device__ __forceinline__ uint32_t smem_addr(const void* p) {
    return (uint32_t)__cvta_generic_to_shared(p);
}
#define CP_ASYNC16(dst, src) \
    asm volatile("cp.async.cg.shared.global [%0], [%1], 16;" :: "r"(dst), "l"(src))
#define CP_ASYNC16Z(dst, src, sz) \
    asm volatile("cp.async.cg.shared.global [%0], [%1], 16, %2;" :: "r"(dst), "l"(src), "r"(sz))
#define CP_COMMIT() asm volatile("cp.async.commit_group;")
#define CP_WAIT1()  asm volatile("cp.async.wait_group 1;")
#define CP_WAIT0()  asm volatile("cp.async.wait_group 0;")

// ---------------- merged f32 -> tf32 convert (hidden + qkv_w + proj_w) ----------------
constexpr int CVT_N1 = N_TOK * D / 4;
constexpr int CVT_N2 = D * 3 * D / 4;
constexpr int CVT_N3 = D * D / 4;
constexpr int CVT_TOT = CVT_N1 + CVT_N2 + CVT_N3;

__global__ void __launch_bounds__(256) convert_all_kernel(
    const float* __restrict__ hid, const float* __restrict__ qw,
    const float* __restrict__ pw,
    uint32_t* __restrict__ hidtf, uint32_t* __restrict__ qwtf,
    uint32_t* __restrict__ pwtf)
{
    const int i = blockIdx.x * blockDim.x + threadIdx.x;
    if (i >= CVT_TOT) return;
    const float* s;
    uint32_t* d;
    int j = i;
    if (j < CVT_N1)            { s = hid; d = hidtf; }
    else if ((j -= CVT_N1) < CVT_N2) { s = qw; d = qwtf; }
    else                       { j -= CVT_N2; s = pw; d = pwtf; }
    const float4 x = reinterpret_cast<const float4*>(s)[j];
    uint4 y;
    y.x = f2tf32(x.x); y.y = f2tf32(x.y); y.z = f2tf32(x.z); y.w = f2tf32(x.w);
    reinterpret_cast<uint4*>(d)[j] = y;
}

// ---------------- tf32 GEMM v128: BM=128, BN=128, 3-stage cp.async ----------------
constexpr int ASTR = 36;
constexpr int BSTR1 = 136;
constexpr int A_WORDS = 128 * ASTR;
constexpr int B_WORDS1 = 32 * BSTR1;
constexpr int STAGE1 = A_WORDS + B_WORDS1;
constexpr int GEMM_SMEM1 = 3 * STAGE1 * 4;

template<int NN, int KD>
__global__ void __launch_bounds__(256) tgemm128_kernel(
    const uint32_t* __restrict__ A, const uint32_t* __restrict__ B,
    const float* __restrict__ bias, float* __restrict__ C)
{
    extern __shared__ uint32_t smem[];

    const int tid  = threadIdx.x;
    const int lane = tid & 31;
    const int w    = tid >> 5;
    const int g    = lane >> 2;
    const int qd   = lane & 3;
    const int wm   = w >> 2;
    const int wn   = w & 3;
    const int bm   = blockIdx.y * 128;
    const int bn   = blockIdx.x * 128;

    const int ar = tid >> 1;
    const int ah = (tid & 1) * 16;
    const int br = tid >> 3;
    const int bc = tid & 7;

    auto issue = [&](int kt) {
        const int k0 = kt * 32;
        uint32_t* as = smem + (kt % 3) * STAGE1;
        uint32_t* bs = as + A_WORDS;
        #pragma unroll
        for (int i = 0; i < 4; i++) {
            const uint32_t dst = smem_addr(&as[ar * ASTR + ah + i * 4]);
            CP_ASYNC16(dst, &A[(size_t)(bm + ar) * KD + k0 + ah + i * 4]);
        }
        #pragma unroll
        for (int i = 0; i < 4; i++) {
            const int col = (bc + 8 * i) * 4;
            const uint32_t dst = smem_addr(&bs[br * BSTR1 + col]);
            CP_ASYNC16(dst, &B[(size_t)(k0 + br) * NN + bn + col]);
        }
        CP_COMMIT();
    };

    float acc[4][4][4] = {};

    issue(0);
    issue(1);

    constexpr int KT = KD / 32;
    for (int kt = 0; kt < KT; kt++) {
        CP_WAIT1();
        __syncthreads();
        if (kt + 2 < KT) issue(kt + 2);

        const uint32_t* as = smem + (kt % 3) * STAGE1;
        const uint32_t* bs = as + A_WORDS;

        #pragma unroll
        for (int kk = 0; kk < 32; kk += 8) {
            uint32_t af[4][4], bf[4][2];
            #pragma unroll
            for (int mi = 0; mi < 4; mi++) {
                const int r0 = (wm * 64 + mi * 16 + g) * ASTR;
                af[mi][0] = as[r0 + kk + qd];
                af[mi][1] = as[r0 + 8 * ASTR + kk + qd];
                af[mi][2] = as[r0 + kk + 4 + qd];
                af[mi][3] = as[r0 + 8 * ASTR + kk + 4 + qd];
            }
            #pragma unroll
            for (int ni = 0; ni < 4; ni++) {
                const int c0 = wn * 32 + ni * 8 + g;
                bf[ni][0] = bs[(kk + qd) * BSTR1 + c0];
                bf[ni][1] = bs[(kk + 4 + qd) * BSTR1 + c0];
            }
            #pragma unroll
            for (int mi = 0; mi < 4; mi++)
                #pragma unroll
                for (int ni = 0; ni < 4; ni++)
                    mma_tf32(acc[mi][ni], af[mi], bf[ni]);
        }
        __syncthreads();
    }

    #pragma unroll
    for (int mi = 0; mi < 4; mi++) {
        const int row = bm + wm * 64 + mi * 16 + g;
        #pragma unroll
        for (int ni = 0; ni < 4; ni++) {
            const int col = bn + wn * 32 + ni * 8 + 2 * qd;
            const float2 bb = *reinterpret_cast<const float2*>(&bias[col]);
            float2 o0, o1;
            o0.x = acc[mi][ni][0] + bb.x; o0.y = acc[mi][ni][1] + bb.y;
            o1.x = acc[mi][ni][2] + bb.x; o1.y = acc[mi][ni][3] + bb.y;
            *reinterpret_cast<float2*>(&C[(size_t)row * NN + col]) = o0;
            *reinterpret_cast<float2*>(&C[(size_t)(row + 8) * NN + col]) = o1;
        }
    }
}

// ---------------- tf32 GEMM v256: BM=128, BN=256 (single-wave proj) ----------------
constexpr int BSTR2 = 264;
constexpr int B_WORDS2 = 32 * BSTR2;
constexpr int STAGE2 = A_WORDS + B_WORDS2;
constexpr int GEMM_SMEM2 = 3 * STAGE2 * 4;

template<int NN, int KD>
__global__ void __launch_bounds__(256) tgemm256_kernel(
    const uint32_t* __restrict__ A, const uint32_t* __restrict__ B,
    const float* __restrict__ bias, float* __restrict__ C)
{
    extern __shared__ uint32_t smem[];

    const int tid  = threadIdx.x;
    const int lane = tid & 31;
    const int w    = tid >> 5;
    const int g    = lane >> 2;
    const int qd   = lane & 3;
    const int wm   = w >> 2;
    const int wn   = w & 3;
    const int bm   = blockIdx.y * 128;
    const int bn   = blockIdx.x * 256;

    const int ar = tid >> 1;
    const int ah = (tid & 1) * 16;
    const int br = tid >> 3;
    const int bc = tid & 7;

    auto issue = [&](int kt) {
        const int k0 = kt * 32;
        uint32_t* as = smem + (kt % 3) * STAGE2;
        uint32_t* bs = as + A_WORDS;
        #pragma unroll
        for (int i = 0; i < 4; i++) {
            const uint32_t dst = smem_addr(&as[ar * ASTR + ah + i * 4]);
            CP_ASYNC16(dst, &A[(size_t)(bm + ar) * KD + k0 + ah + i * 4]);
        }
        #pragma unroll
        for (int i = 0; i < 8; i++) {
            const int col = (bc + 8 * i) * 4;
            const uint32_t dst = smem_addr(&bs[br * BSTR2 + col]);
            CP_ASYNC16(dst, &B[(size_t)(k0 + br) * NN + bn + col]);
        }
        CP_COMMIT();
    };

    float acc[4][8][4] = {};

    issue(0);
    issue(1);

    constexpr int KT = KD / 32;
    for (int kt = 0; kt < KT; kt++) {
        CP_WAIT1();
        __syncthreads();
        if (kt + 2 < KT) issue(kt + 2);

        const uint32_t* as = smem + (kt % 3) * STAGE2;
        const uint32_t* bs = as + A_WORDS;

        #pragma unroll
        for (int kk = 0; kk < 32; kk += 8) {
            uint32_t af[4][4], bf[8][2];
            #pragma unroll
            for (int mi = 0; mi < 4; mi++) {
                const int r0 = (wm * 64 + mi * 16 + g) * ASTR;
                af[mi][0] = as[r0 + kk + qd];
                af[mi][1] = as[r0 + 8 * ASTR + kk + qd];
                af[mi][2] = as[r0 + kk + 4 + qd];
                af[mi][3] = as[r0 + 8 * ASTR + kk + 4 + qd];
            }
            #pragma unroll
            for (int ni = 0; ni < 8; ni++) {
                const int c0 = wn * 64 + ni * 8 + g;
                bf[ni][0] = bs[(kk + qd) * BSTR2 + c0];
                bf[ni][1] = bs[(kk + 4 + qd) * BSTR2 + c0];
            }
            #pragma unroll
            for (int mi = 0; mi < 4; mi++)
                #pragma unroll
                for (int ni = 0; ni < 8; ni++)
                    mma_tf32(acc[mi][ni], af[mi], bf[ni]);
        }
        __syncthreads();
    }

    #pragma unroll
    for (int mi = 0; mi < 4; mi++) {
        const int row = bm + wm * 64 + mi * 16 + g;
        #pragma unroll
        for (int ni = 0; ni < 8; ni++) {
            const int col = bn + wn * 64 + ni * 8 + 2 * qd;
            const float2 bb = *reinterpret_cast<const float2*>(&bias[col]);
            float2 o0, o1;
            o0.x = acc[mi][ni][0] + bb.x; o0.y = acc[mi][ni][1] + bb.y;
            o1.x = acc[mi][ni][2] + bb.x; o1.y = acc[mi][ni][3] + bb.y;
            *reinterpret_cast<float2*>(&C[(size_t)row * NN + col]) = o0;
            *reinterpret_cast<float2*>(&C[(size_t)(row + 8) * NN + col]) = o1;
        }
    }
}

// ---------------- RoPE + split + bf16 hi/lo (q/k) + tf32 (v) ----------------
__global__ void __launch_bounds__(256) rope_split_kernel(
    const float* __restrict__ qkv, const float* __restrict__ cosNK,
    const float* __restrict__ sinNK,
    uint32_t* __restrict__ qhib, uint32_t* __restrict__ qlob,
    uint32_t* __restrict__ khib, uint32_t* __restrict__ klob,
    uint32_t* __restrict__ vtf)
{
    const int idx = blockIdx.x * blockDim.x + threadIdx.x;
    if (idx >= N_TOK * H * WPR) return;
    const int wd = idx % WPR;
    const int h  = (idx / WPR) % H;
    const int n  = idx / (WPR * H);

    const float* base = qkv + (size_t)n * 3 * H * HK;

    float qr[2], kr[2], vv[2];
    #pragma unroll
    for (int e = 0; e < 2; e++) {
        const int kk = 2 * wd + e;
        const float c = cosNK[n * HK + kk];
        const float s = sinNK[n * HK + kk];
        const int off  = h * HK + kk;
        const int krot = (kk < HK / 2) ? kk + HK / 2 : kk - HK / 2;
        const float sg = (kk < HK / 2) ? -1.f : 1.f;
        const int offr = h * HK + krot;
        const float qv  = base[off];
        const float kv  = base[H * HK + off];
        vv[e]           = base[2 * H * HK + off];
        const float qvr = base[offr];
        const float kvr = base[H * HK + offr];
        qr[e] = (qv * c + sg * qvr * s) * SCALE;
        kr[e] = kv * c + sg * kvr * s;
    }

    uint32_t qh[2], ql[2], kh[2], kl[2];
    #pragma unroll
    for (int e = 0; e < 2; e++) {
        qh[e] = bf16bits(qr[e]);
        ql[e] = bf16bits(qr[e] - bf16val(qh[e]));
        kh[e] = bf16bits(kr[e]);
        kl[e] = bf16bits(kr[e] - bf16val(kh[e]));
    }

    const size_t ow = (size_t)h * N_TOK * WPR + (size_t)n * WPR + wd;
    qhib[ow] = (qh[1] << 16) | qh[0];
    qlob[ow] = (ql[1] << 16) | ql[0];
    khib[ow] = (kh[1] << 16) | kh[0];
    klob[ow] = (kl[1] << 16) | kl[0];

    const size_t ov = (size_t)h * N_TOK * HK + (size_t)n * HK + 2 * wd;
    vtf[ov]     = f2tf32(vv[0]);
    vtf[ov + 1] = f2tf32(vv[1]);
}

// ---------------- mma flash attention: QTQ=128, 8 warps, KTK=64 ----------------
constexpr int QTQ  = 128;  // queries per block
constexpr int NWRP = 8;    // warps per block
constexpr int KTK  = 64;
constexpr int QSTR = 44;   // k smem stride (packed bf16x2 words)
constexpr int VSTR = 88;   // v smem stride
constexpr int PST  = 68;   // P stride

constexpr int ATT_SMEM_WORDS =
    2 * KTK * QSTR        // khi double-buffered   5632
    + 2 * KTK * QSTR      // klo                    5632
    + 2 * KTK * VSTR      // v                     11264
    + NWRP * 16 * PST     // P (per warp)           8704
    + 2 * QTQ + 2;        // rs, re, blk

__global__ void __launch_bounds__(256, 1) attn_mma_kernel(
    const uint32_t* __restrict__ gqhi, const uint32_t* __restrict__ gqlo,
    const uint32_t* __restrict__ gkhi, const uint32_t* __restrict__ gklo,
    const uint32_t* __restrict__ gvtf, const int* __restrict__ cu,
    uint32_t* __restrict__ attn_tf)
{
    extern __shared__ uint32_t sm[];
    uint32_t* khiS = sm;
    uint32_t* kloS = khiS + 2 * KTK * QSTR;
    uint32_t* vS   = kloS + 2 * KTK * QSTR;
    uint32_t* pS   = vS + 2 * KTK * VSTR;
    int*      rs   = (int*)(pS + NWRP * 16 * PST);
    int*      re   = rs + QTQ;
    int*      blk  = re + QTQ;

    const int h    = blockIdx.y;
    const int q0   = blockIdx.x * QTQ;
    const int tid  = threadIdx.x;
    const int w    = tid >> 5;          // 0..7
    const int lane = tid & 31;
    const int g    = lane >> 2;
    const int qd   = lane & 3;

    if (tid < QTQ) {
        const int n = q0 + tid;
        int lo = 0, hi = N_TOK;
        #pragma unroll
        for (int sgi = 0; sgi < NSEG; sgi++) {
            const int a = cu[sgi], b = cu[sgi + 1];
            if (n >= a && n < b) { lo = a; hi = b; }
        }
        rs[tid] = lo; re[tid] = hi;
    }
    __syncthreads();
    if (tid == 0) {
        int lo = rs[0], hi = re[0];
        #pragma unroll
        for (int r = 1; r < QTQ; r++) { lo = min(lo, rs[r]); hi = max(hi, re[r]); }
        blk[0] = lo; blk[1] = hi;
    }

    int wlo = N_TOK, whi = 0, wrs_max = 0, wre_min = N_TOK;
    #pragma unroll
    for (int r = 0; r < 16; r++) {
        const int a = rs[w * 16 + r], b = re[w * 16 + r];
        wlo = min(wlo, a); whi = max(whi, b);
        wrs_max = max(wrs_max, a); wre_min = min(wre_min, b);
    }
    const int rowA = w * 16 + g, rowB = rowA + 8;
    const int rsA = rs[rowA], reA = re[rowA];
    const int rsB = rs[rowB], reB = re[rowB];

    const size_t hb40 = (size_t)h * N_TOK * WPR;
    const size_t hb80 = (size_t)h * N_TOK * HK;
    uint32_t qh[5][4], ql[5][4];
    #pragma unroll
    for (int sl = 0; sl < 5; sl++) {
        const size_t bA = hb40 + (size_t)(q0 + rowA) * WPR + sl * 8;
        const size_t bB = hb40 + (size_t)(q0 + rowB) * WPR + sl * 8;
        qh[sl][0] = gqhi[bA + qd];     qh[sl][1] = gqhi[bB + qd];
        qh[sl][2] = gqhi[bA + 4 + qd]; qh[sl][3] = gqhi[bB + 4 + qd];
        ql[sl][0] = gqlo[bA + qd];     ql[sl][1] = gqlo[bB + qd];
        ql[sl][2] = gqlo[bA + 4 + qd]; ql[sl][3] = gqlo[bB + 4 + qd];
    }
    __syncthreads();
    const int lo = blk[0], hi = blk[1];

    auto stageKV = [&](int kc, int buf) {
        uint32_t* kh_ = khiS + buf * KTK * QSTR;
        uint32_t* kl_ = kloS + buf * KTK * QSTR;
        uint32_t* v_  = vS + buf * KTK * VSTR;
        for (int i = tid; i < KTK * 10; i += 256) {       // 640 k-uint4s
            const int r = i / 10, c = (i % 10) * 4;
            const int m = kc + r;
            const uint32_t sz = (m < hi) ? 16u : 0u;
            const size_t go = hb40 + (size_t)min(m, hi - 1) * WPR + c;
            CP_ASYNC16Z(smem_addr(&kh_[r * QSTR + c]), &gkhi[go], sz);
            CP_ASYNC16Z(smem_addr(&kl_[r * QSTR + c]), &gklo[go], sz);
        }
        #pragma unroll
        for (int it = 0; it < 5; it++) {                  // 1280 v-uint4s
            const int i = it * 256 + tid;
            const int r = i / 20, c = (i % 20) * 4;
            const int m = kc + r;
            const uint32_t sz = (m < hi) ? 16u : 0u;
            const size_t go = hb80 + (size_t)min(m, hi - 1) * HK + c;
            CP_ASYNC16Z(smem_addr(&v_[r * VSTR + c]), &gvtf[go], sz);
        }
        CP_COMMIT();
    };

    float miA = -1e30f, liA = 0.f, miB = -1e30f, liB = 0.f;
    float acc[10][4] = {};
    uint32_t* pw = pS + w * (16 * PST);

    const int T = (hi - lo + KTK - 1) / KTK;
    stageKV(lo, 0);

    for (int t = 0; t < T; t++) {
        const int kc  = lo + t * KTK;
        const int buf = t & 1;
        if (t + 1 < T) { stageKV(kc + KTK, buf ^ 1); CP_WAIT1(); }
        else           { CP_WAIT0(); }
        __syncthreads();

        if (!(kc + KTK <= wlo || kc >= whi)) {
            const uint32_t* kh_ = khiS + buf * KTK * QSTR;
            const uint32_t* kl_ = kloS + buf * KTK * QSTR;
            const uint32_t* v_  = vS + buf * KTK * VSTR;

            // ---- S = Q K^T (3x bf16 hi/lo), 16x64 strip per warp ----
            float s[8][4] = {};
            #pragma unroll
            for (int sl = 0; sl < 5; sl++) {
                const int base = sl * 8;
                #pragma unroll
                for (int nt = 0; nt < 8; nt++) {
                    const int kr = (nt * 8 + g) * QSTR + base;
                    uint32_t bh[2], bl[2];
                    bh[0] = kh_[kr + qd]; bh[1] = kh_[kr + 4 + qd];
                    bl[0] = kl_[kr + qd]; bl[1] = kl_[kr + 4 + qd];
                    mma_bf16(s[nt], qh[sl], bh);
                    mma_bf16(s[nt], qh[sl], bl);
                    mma_bf16(s[nt], ql[sl], bh);
                }
            }

            // ---- softmax: fast path interior / masked path at boundaries ----
            float mxA = -1e30f, mxB = -1e30f, sumA = 0.f, sumB = 0.f;
            float nmA, nmB;
            const bool full = (kc >= wrs_max) && (kc + KTK <= wre_min);
            if (full) {
                #pragma unroll
                for (int nt = 0; nt < 8; nt++) {
                    mxA = fmaxf(mxA, fmaxf(s[nt][0], s[nt][1]));
                    mxB = fmaxf(mxB, fmaxf(s[nt][2], s[nt][3]));
                }
                #pragma unroll
                for (int off = 1; off <= 2; off <<= 1) {
                    mxA = fmaxf(mxA, __shfl_xor_sync(0xffffffffu, mxA, off));
                    mxB = fmaxf(mxB, __shfl_xor_sync(0xffffffffu, mxB, off));
                }
                nmA = fmaxf(miA, mxA); nmB = fmaxf(miB, mxB);
                #pragma unroll
                for (int nt = 0; nt < 8; nt++) {
                    s[nt][0] = __expf(s[nt][0] - nmA);
                    s[nt][1] = __expf(s[nt][1] - nmA);
                    s[nt][2] = __expf(s[nt][2] - nmB);
                    s[nt][3] = __expf(s[nt][3] - nmB);
                    sumA += s[nt][0] + s[nt][1];
                    sumB += s[nt][2] + s[nt][3];
                }
            } else {
                #pragma unroll
                for (int nt = 0; nt < 8; nt++) {
                    const int c0 = kc + nt * 8 + 2 * qd;
                    const int c1 = c0 + 1;
                    mxA = fmaxf(mxA, fmaxf((c0 >= rsA && c0 < reA) ? s[nt][0] : -1e30f,
                                           (c1 >= rsA && c1 < reA) ? s[nt][1] : -1e30f));
                    mxB = fmaxf(mxB, fmaxf((c0 >= rsB && c0 < reB) ? s[nt][2] : -1e30f,
                                           (c1 >= rsB && c1 < reB) ? s[nt][3] : -1e30f));
                }
                #pragma unroll
                for (int off = 1; off <= 2; off <<= 1) {
                    mxA = fmaxf(mxA, __shfl_xor_sync(0xffffffffu, mxA, off));
                    mxB = fmaxf(mxB, __shfl_xor_sync(0xffffffffu, mxB, off));
                }
                nmA = fmaxf(miA, mxA); nmB = fmaxf(miB, mxB);
                #pragma unroll
                for (int nt = 0; nt < 8; nt++) {
                    const int c0 = kc + nt * 8 + 2 * qd;
                    const int c1 = c0 + 1;
                    s[nt][0] = (c0 >= rsA && c0 < reA) ? __expf(s[nt][0] - nmA) : 0.f;
                    s[nt][1] = (c1 >= rsA && c1 < reA) ? __expf(s[nt][1] - nmA) : 0.f;
                    s[nt][2] = (c0 >= rsB && c0 < reB) ? __expf(s[nt][2] - nmB) : 0.f;
                    s[nt][3] = (c1 >= rsB && c1 < reB) ? __expf(s[nt][3] - nmB) : 0.f;
                    sumA += s[nt][0] + s[nt][1];
                    sumB += s[nt][2] + s[nt][3];
                }
            }
            #pragma unroll
            for (int off = 1; off <= 2; off <<= 1) {
                sumA += __shfl_xor_sync(0xffffffffu, sumA, off);
                sumB += __shfl_xor_sync(0xffffffffu, sumB, off);
            }

            // ---- exact no-op rescale skip: cr == 1.0 iff nm == mi ----
            if (nmA != miA || nmB != miB) {
                const float crA = __expf(miA - nmA);
                const float crB = __expf(miB - nmB);
                liA = liA * crA; liB = liB * crB;
                #pragma unroll
                for (int nt = 0; nt < 10; nt++) {
                    acc[nt][0] *= crA; acc[nt][1] *= crA;
                    acc[nt][2] *= crB; acc[nt][3] *= crB;
                }
                miA = nmA; miB = nmB;
            }
            liA += sumA; liB += sumB;

            // ---- P -> warp-private smem (tf32), then PV (tf32) ----
            #pragma unroll
            for (int nt = 0; nt < 8; nt++) {
                const int cb = nt * 8 + 2 * qd;
                uint2 pa, pb;
                pa.x = f2tf32(s[nt][0]); pa.y = f2tf32(s[nt][1]);
                pb.x = f2tf32(s[nt][2]); pb.y = f2tf32(s[nt][3]);
                *reinterpret_cast<uint2*>(&pw[g * PST + cb])       = pa;
                *reinterpret_cast<uint2*>(&pw[(g + 8) * PST + cb]) = pb;
            }
            __syncwarp();

            #pragma unroll
            for (int k8 = 0; k8 < KTK; k8 += 8) {
                uint32_t a[4];
                a[0] = pw[g * PST + k8 + qd];
                a[1] = pw[(g + 8) * PST + k8 + qd];
                a[2] = pw[g * PST + k8 + 4 + qd];
                a[3] = pw[(g + 8) * PST + k8 + 4 + qd];
                #pragma unroll
                for (int nt = 0; nt < 10; nt++) {
                    uint32_t b[2];
                    b[0] = v_[(k8 + qd) * VSTR + nt * 8 + g];
                    b[1] = v_[(k8 + 4 + qd) * VSTR + nt * 8 + g];
                    mma_tf32(acc[nt], a, b);
                }
            }
            __syncwarp();
        }
        __syncthreads();
    }

    const float invA = 1.f / liA, invB = 1.f / liB;
    uint32_t* dA = attn_tf + (size_t)(q0 + rowA) * D + h * HK;
    uint32_t* dB = attn_tf + (size_t)(q0 + rowB) * D + h * HK;
    #pragma unroll
    for (int nt = 0; nt < 10; nt++) {
        const int col = nt * 8 + 2 * qd;
        dA[col]     = f2tf32(acc[nt][0] * invA);
        dA[col + 1] = f2tf32(acc[nt][1] * invA);
        dB[col]     = f2tf32(acc[nt][2] * invB);
        dB[col + 1] = f2tf32(acc[nt][3] * invB);
    }
}

// ---------------- launch ----------------
extern "C" void kernel_launch(void* const* d_in, const int* in_sizes, int n_in,
                              void* d_out, int out_size)
{
    const float* hidden = (const float*)d_in[0];
    const int*   cu     = (const int*)  d_in[1];
    const float* cosNK  = (const float*)d_in[2];
    const float* sinNK  = (const float*)d_in[3];
    const float* qkv_w  = (const float*)d_in[4];
    const float* qkv_b  = (const float*)d_in[5];
    const float* proj_w = (const float*)d_in[6];
    const float* proj_b = (const float*)d_in[7];
    float* out = (float*)d_out;

    float *qkv;
    uint32_t *hidtf, *qkvwtf, *projwtf, *qhib, *qlob, *khib, *klob, *vtf, *attntf;
    cudaGetSymbolAddress((void**)&hidtf,  g_hid_tf);
    cudaGetSymbolAddress((void**)&qkvwtf, g_qkvw_tf);
    cudaGetSymbolAddress((void**)&projwtf,g_projw_tf);
    cudaGetSymbolAddress((void**)&qkv,    g_qkv);
    cudaGetSymbolAddress((void**)&qhib,   g_qhib);
    cudaGetSymbolAddress((void**)&qlob,   g_qlob);
    cudaGetSymbolAddress((void**)&khib,   g_khib);
    cudaGetSymbolAddress((void**)&klob,   g_klob);
    cudaGetSymbolAddress((void**)&vtf,    g_vtf);
    cudaGetSymbolAddress((void**)&attntf, g_attn_tf);

    const size_t attn_smem = ATT_SMEM_WORDS * sizeof(uint32_t);
    static bool attr_done = false;
    if (!attr_done) {
        cudaFuncSetAttribute(tgemm128_kernel<3 * D, D>,
                             cudaFuncAttributeMaxDynamicSharedMemorySize, GEMM_SMEM1);
        cudaFuncSetAttribute(tgemm256_kernel<D, D>,
                             cudaFuncAttributeMaxDynamicSharedMemorySize, GEMM_SMEM2);
        cudaFuncSetAttribute(attn_mma_kernel,
                             cudaFuncAttributeMaxDynamicSharedMemorySize, (int)attn_smem);
        attr_done = true;
    }

    // 0) merged converts
    convert_all_kernel<<<(CVT_TOT + 255) / 256, 256>>>(
        hidden, qkv_w, proj_w, hidtf, qkvwtf, projwtf);

    // 1) QKV GEMM + bias
    tgemm128_kernel<3 * D, D><<<dim3((3 * D) / 128, N_TOK / 128), 256, GEMM_SMEM1>>>(
        hidtf, qkvwtf, qkv_b, qkv);

    // 2) RoPE + split
    rope_split_kernel<<<(N_TOK * H * WPR + 255) / 256, 256>>>(
        qkv, cosNK, sinNK, qhib, qlob, khib, klob, vtf);

    // 3) attention (QTQ=128, 8 warps, KTK=64)
    attn_mma_kernel<<<dim3(N_TOK / QTQ, H), 256, attn_smem>>>(
        qhib, qlob, khib, klob, vtf, cu, attntf);

    // 4) projection GEMM + bias -> d_out
    tgemm256_kernel<D, D><<<dim3(D / 256, N_TOK / 128), 256, GEMM_SMEM2>>>(
        attntf, projwtf, proj_b, out);
}

// round 16
// speedup vs baseline: 1.0489x; 1.0489x over previous
#include <cuda_runtime.h>
#include <cuda_bf16.h>
#include <cstdint>

// Problem constants
constexpr int N_TOK = 3072;
constexpr int D     = 1280;
constexpr int H     = 16;
constexpr int HK    = 80;     // head dim
constexpr int WPR   = HK / 2; // packed bf16 words per row (40)
constexpr int NSEG  = 8;
constexpr float SCALE = 0.111803398874989485f; // 80^-0.5

// ---------------- scratch ----------------
__device__ uint32_t g_hid_tf[N_TOK * D];        // tf32 of hidden
__device__ uint32_t g_qkvw_tf[D * 3 * D];       // tf32 of qkv_w
__device__ uint32_t g_projw_tf[D * D];          // tf32 of proj_w
__device__ float    g_qkv[N_TOK * 3 * D];       // [N][3][H][K] fp32
__device__ uint32_t g_qhib[H * N_TOK * WPR];    // bf16x2 hi of SCALE*rope(q)
__device__ uint32_t g_qlob[H * N_TOK * WPR];
__device__ uint32_t g_khib[H * N_TOK * WPR];
__device__ uint32_t g_klob[H * N_TOK * WPR];
__device__ uint32_t g_vtf[H * N_TOK * HK];      // tf32 v
__device__ uint32_t g_attn_tf[N_TOK * D];       // tf32 attn out [N][H*K]

// ---------------- helpers ----------------
__device__ __forceinline__ uint32_t f2tf32(float x) {
    uint32_t r;
    asm("cvt.rna.tf32.f32 %0, %1;" : "=r"(r) : "f"(x));
    return r;
}
__device__ __forceinline__ void mma_tf32(float c[4], const uint32_t a[4], const uint32_t b[2]) {
    asm volatile(
        "mma.sync.aligned.m16n8k8.row.col.f32.tf32.tf32.f32 "
        "{%0,%1,%2,%3}, {%4,%5,%6,%7}, {%8,%9}, {%0,%1,%2,%3};"
        : "+f"(c[0]), "+f"(c[1]), "+f"(c[2]), "+f"(c[3])
        : "r"(a[0]), "r"(a[1]), "r"(a[2]), "r"(a[3]), "r"(b[0]), "r"(b[1]));
}
__device__ __forceinline__ void mma_bf16(float c[4], const uint32_t a[4], const uint32_t b[2]) {
    asm volatile(
        "mma.sync.aligned.m16n8k16.row.col.f32.bf16.bf16.f32 "
        "{%0,%1,%2,%3}, {%4,%5,%6,%7}, {%8,%9}, {%0,%1,%2,%3};"
        : "+f"(c[0]), "+f"(c[1]), "+f"(c[2]), "+f"(c[3])
        : "r"(a[0]), "r"(a[1]), "r"(a[2]), "r"(a[3]), "r"(b[0]), "r"(b[1]));
}
__device__ __forceinline__ uint32_t bf16bits(float x) {
    const __nv_bfloat16 b = __float2bfloat16(x);
    return (uint32_t)*reinterpret_cast<const uint16_t*>(&b);
}
__device__ __forceinline__ float bf16val(uint32_t bits) {
    const uint16_t u = (uint16_t)bits;
    return __bfloat162float(*reinterpret_cast<const __nv_bfloat16*>(&u));
}
__device__ __forceinline__ uint32_t smem_addr(const void* p) {
    return (uint32_t)__cvta_generic_to_shared(p);
}
#define CP_ASYNC16(dst, src) \
    asm volatile("cp.async.cg.shared.global [%0], [%1], 16;" :: "r"(dst), "l"(src))
#define CP_ASYNC16Z(dst, src, sz) \
    asm volatile("cp.async.cg.shared.global [%0], [%1], 16, %2;" :: "r"(dst), "l"(src), "r"(sz))
#define CP_COMMIT() asm volatile("cp.async.commit_group;")
#define CP_WAIT1()  asm volatile("cp.async.wait_group 1;")
#define CP_WAIT0()  asm volatile("cp.async.wait_group 0;")

// ---------------- merged f32 -> tf32 convert (hidden + qkv_w + proj_w) ----------------
constexpr int CVT_N1 = N_TOK * D / 4;
constexpr int CVT_N2 = D * 3 * D / 4;
constexpr int CVT_N3 = D * D / 4;
constexpr int CVT_TOT = CVT_N1 + CVT_N2 + CVT_N3;

__global__ void __launch_bounds__(256) convert_all_kernel(
    const float* __restrict__ hid, const float* __restrict__ qw,
    const float* __restrict__ pw,
    uint32_t* __restrict__ hidtf, uint32_t* __restrict__ qwtf,
    uint32_t* __restrict__ pwtf)
{
    const int i = blockIdx.x * blockDim.x + threadIdx.x;
    if (i >= CVT_TOT) return;
    const float* s;
    uint32_t* d;
    int j = i;
    if (j < CVT_N1)            { s = hid; d = hidtf; }
    else if ((j -= CVT_N1) < CVT_N2) { s = qw; d = qwtf; }
    else                       { j -= CVT_N2; s = pw; d = pwtf; }
    const float4 x = reinterpret_cast<const float4*>(s)[j];
    uint4 y;
    y.x = f2tf32(x.x); y.y = f2tf32(x.y); y.z = f2tf32(x.z); y.w = f2tf32(x.w);
    reinterpret_cast<uint4*>(d)[j] = y;
}

// ---------------- tf32 GEMM v128: BM=128, BN=128, 3-stage cp.async, 1 barrier/tile ----------------
constexpr int ASTR = 36;
constexpr int BSTR1 = 136;
constexpr int A_WORDS = 128 * ASTR;
constexpr int B_WORDS1 = 32 * BSTR1;
constexpr int STAGE1 = A_WORDS + B_WORDS1;
constexpr int GEMM_SMEM1 = 3 * STAGE1 * 4;

template<int NN, int KD>
__global__ void __launch_bounds__(256) tgemm128_kernel(
    const uint32_t* __restrict__ A, const uint32_t* __restrict__ B,
    const float* __restrict__ bias, float* __restrict__ C)
{
    extern __shared__ uint32_t smem[];

    const int tid  = threadIdx.x;
    const int lane = tid & 31;
    const int w    = tid >> 5;
    const int g    = lane >> 2;
    const int qd   = lane & 3;
    const int wm   = w >> 2;
    const int wn   = w & 3;
    const int bm   = blockIdx.y * 128;
    const int bn   = blockIdx.x * 128;

    const int ar = tid >> 1;
    const int ah = (tid & 1) * 16;
    const int br = tid >> 3;
    const int bc = tid & 7;

    auto issue = [&](int kt) {
        const int k0 = kt * 32;
        uint32_t* as = smem + (kt % 3) * STAGE1;
        uint32_t* bs = as + A_WORDS;
        #pragma unroll
        for (int i = 0; i < 4; i++) {
            const uint32_t dst = smem_addr(&as[ar * ASTR + ah + i * 4]);
            CP_ASYNC16(dst, &A[(size_t)(bm + ar) * KD + k0 + ah + i * 4]);
        }
        #pragma unroll
        for (int i = 0; i < 4; i++) {
            const int col = (bc + 8 * i) * 4;
            const uint32_t dst = smem_addr(&bs[br * BSTR1 + col]);
            CP_ASYNC16(dst, &B[(size_t)(k0 + br) * NN + bn + col]);
        }
        CP_COMMIT();
    };

    float acc[4][4][4] = {};

    issue(0);
    issue(1);

    constexpr int KT = KD / 32;
    for (int kt = 0; kt < KT; kt++) {
        CP_WAIT1();
        __syncthreads();
        if (kt + 2 < KT) issue(kt + 2);

        const uint32_t* as = smem + (kt % 3) * STAGE1;
        const uint32_t* bs = as + A_WORDS;

        #pragma unroll
        for (int kk = 0; kk < 32; kk += 8) {
            uint32_t af[4][4], bf[4][2];
            #pragma unroll
            for (int mi = 0; mi < 4; mi++) {
                const int r0 = (wm * 64 + mi * 16 + g) * ASTR;
                af[mi][0] = as[r0 + kk + qd];
                af[mi][1] = as[r0 + 8 * ASTR + kk + qd];
                af[mi][2] = as[r0 + kk + 4 + qd];
                af[mi][3] = as[r0 + 8 * ASTR + kk + 4 + qd];
            }
            #pragma unroll
            for (int ni = 0; ni < 4; ni++) {
                const int c0 = wn * 32 + ni * 8 + g;
                bf[ni][0] = bs[(kk + qd) * BSTR1 + c0];
                bf[ni][1] = bs[(kk + 4 + qd) * BSTR1 + c0];
            }
            #pragma unroll
            for (int mi = 0; mi < 4; mi++)
                #pragma unroll
                for (int ni = 0; ni < 4; ni++)
                    mma_tf32(acc[mi][ni], af[mi], bf[ni]);
        }
        // no trailing barrier: buffer kt%3 is next written by issue(kt+3) at
        // iteration kt+1, which is AFTER that iteration's CP_WAIT1+__syncthreads.
    }

    #pragma unroll
    for (int mi = 0; mi < 4; mi++) {
        const int row = bm + wm * 64 + mi * 16 + g;
        #pragma unroll
        for (int ni = 0; ni < 4; ni++) {
            const int col = bn + wn * 32 + ni * 8 + 2 * qd;
            const float2 bb = *reinterpret_cast<const float2*>(&bias[col]);
            float2 o0, o1;
            o0.x = acc[mi][ni][0] + bb.x; o0.y = acc[mi][ni][1] + bb.y;
            o1.x = acc[mi][ni][2] + bb.x; o1.y = acc[mi][ni][3] + bb.y;
            *reinterpret_cast<float2*>(&C[(size_t)row * NN + col]) = o0;
            *reinterpret_cast<float2*>(&C[(size_t)(row + 8) * NN + col]) = o1;
        }
    }
}

// ---------------- tf32 GEMM v256: BM=128, BN=256 (single-wave proj), 1 barrier/tile ----------------
constexpr int BSTR2 = 264;
constexpr int B_WORDS2 = 32 * BSTR2;
constexpr int STAGE2 = A_WORDS + B_WORDS2;
constexpr int GEMM_SMEM2 = 3 * STAGE2 * 4;

template<int NN, int KD>
__global__ void __launch_bounds__(256) tgemm256_kernel(
    const uint32_t* __restrict__ A, const uint32_t* __restrict__ B,
    const float* __restrict__ bias, float* __restrict__ C)
{
    extern __shared__ uint32_t smem[];

    const int tid  = threadIdx.x;
    const int lane = tid & 31;
    const int w    = tid >> 5;
    const int g    = lane >> 2;
    const int qd   = lane & 3;
    const int wm   = w >> 2;
    const int wn   = w & 3;
    const int bm   = blockIdx.y * 128;
    const int bn   = blockIdx.x * 256;

    const int ar = tid >> 1;
    const int ah = (tid & 1) * 16;
    const int br = tid >> 3;
    const int bc = tid & 7;

    auto issue = [&](int kt) {
        const int k0 = kt * 32;
        uint32_t* as = smem + (kt % 3) * STAGE2;
        uint32_t* bs = as + A_WORDS;
        #pragma unroll
        for (int i = 0; i < 4; i++) {
            const uint32_t dst = smem_addr(&as[ar * ASTR + ah + i * 4]);
            CP_ASYNC16(dst, &A[(size_t)(bm + ar) * KD + k0 + ah + i * 4]);
        }
        #pragma unroll
        for (int i = 0; i < 8; i++) {
            const int col = (bc + 8 * i) * 4;
            const uint32_t dst = smem_addr(&bs[br * BSTR2 + col]);
            CP_ASYNC16(dst, &B[(size_t)(k0 + br) * NN + bn + col]);
        }
        CP_COMMIT();
    };

    float acc[4][8][4] = {};

    issue(0);
    issue(1);

    constexpr int KT = KD / 32;
    for (int kt = 0; kt < KT; kt++) {
        CP_WAIT1();
        __syncthreads();
        if (kt + 2 < KT) issue(kt + 2);

        const uint32_t* as = smem + (kt % 3) * STAGE2;
        const uint32_t* bs = as + A_WORDS;

        #pragma unroll
        for (int kk = 0; kk < 32; kk += 8) {
            uint32_t af[4][4], bf[8][2];
            #pragma unroll
            for (int mi = 0; mi < 4; mi++) {
                const int r0 = (wm * 64 + mi * 16 + g) * ASTR;
                af[mi][0] = as[r0 + kk + qd];
                af[mi][1] = as[r0 + 8 * ASTR + kk + qd];
                af[mi][2] = as[r0 + kk + 4 + qd];
                af[mi][3] = as[r0 + 8 * ASTR + kk + 4 + qd];
            }
            #pragma unroll
            for (int ni = 0; ni < 8; ni++) {
                const int c0 = wn * 64 + ni * 8 + g;
                bf[ni][0] = bs[(kk + qd) * BSTR2 + c0];
                bf[ni][1] = bs[(kk + 4 + qd) * BSTR2 + c0];
            }
            #pragma unroll
            for (int mi = 0; mi < 4; mi++)
                #pragma unroll
                for (int ni = 0; ni < 8; ni++)
                    mma_tf32(acc[mi][ni], af[mi], bf[ni]);
        }
        // no trailing barrier (same 3-stage argument as tgemm128)
    }

    #pragma unroll
    for (int mi = 0; mi < 4; mi++) {
        const int row = bm + wm * 64 + mi * 16 + g;
        #pragma unroll
        for (int ni = 0; ni < 8; ni++) {
            const int col = bn + wn * 64 + ni * 8 + 2 * qd;
            const float2 bb = *reinterpret_cast<const float2*>(&bias[col]);
            float2 o0, o1;
            o0.x = acc[mi][ni][0] + bb.x; o0.y = acc[mi][ni][1] + bb.y;
            o1.x = acc[mi][ni][2] + bb.x; o1.y = acc[mi][ni][3] + bb.y;
            *reinterpret_cast<float2*>(&C[(size_t)row * NN + col]) = o0;
            *reinterpret_cast<float2*>(&C[(size_t)(row + 8) * NN + col]) = o1;
        }
    }
}

// ---------------- RoPE + split + bf16 hi/lo (q/k) + tf32 (v) ----------------
__global__ void __launch_bounds__(256) rope_split_kernel(
    const float* __restrict__ qkv, const float* __restrict__ cosNK,
    const float* __restrict__ sinNK,
    uint32_t* __restrict__ qhib, uint32_t* __restrict__ qlob,
    uint32_t* __restrict__ khib, uint32_t* __restrict__ klob,
    uint32_t* __restrict__ vtf)
{
    const int idx = blockIdx.x * blockDim.x + threadIdx.x;
    if (idx >= N_TOK * H * WPR) return;
    const int wd = idx % WPR;
    const int h  = (idx / WPR) % H;
    const int n  = idx / (WPR * H);

    const float* base = qkv + (size_t)n * 3 * H * HK;

    float qr[2], kr[2], vv[2];
    #pragma unroll
    for (int e = 0; e < 2; e++) {
        const int kk = 2 * wd + e;
        const float c = cosNK[n * HK + kk];
        const float s = sinNK[n * HK + kk];
        const int off  = h * HK + kk;
        const int krot = (kk < HK / 2) ? kk + HK / 2 : kk - HK / 2;
        const float sg = (kk < HK / 2) ? -1.f : 1.f;
        const int offr = h * HK + krot;
        const float qv  = base[off];
        const float kv  = base[H * HK + off];
        vv[e]           = base[2 * H * HK + off];
        const float qvr = base[offr];
        const float kvr = base[H * HK + offr];
        qr[e] = (qv * c + sg * qvr * s) * SCALE;
        kr[e] = kv * c + sg * kvr * s;
    }

    uint32_t qh[2], ql[2], kh[2], kl[2];
    #pragma unroll
    for (int e = 0; e < 2; e++) {
        qh[e] = bf16bits(qr[e]);
        ql[e] = bf16bits(qr[e] - bf16val(qh[e]));
        kh[e] = bf16bits(kr[e]);
        kl[e] = bf16bits(kr[e] - bf16val(kh[e]));
    }

    const size_t ow = (size_t)h * N_TOK * WPR + (size_t)n * WPR + wd;
    qhib[ow] = (qh[1] << 16) | qh[0];
    qlob[ow] = (ql[1] << 16) | ql[0];
    khib[ow] = (kh[1] << 16) | kh[0];
    klob[ow] = (kl[1] << 16) | kl[0];

    const size_t ov = (size_t)h * N_TOK * HK + (size_t)n * HK + 2 * wd;
    vtf[ov]     = f2tf32(vv[0]);
    vtf[ov + 1] = f2tf32(vv[1]);
}

// ---------------- mma flash attention: QTQ=64, KTK=64, fast path + rescale skip (R14) ----------------
constexpr int QTQ  = 64;
constexpr int KTK  = 64;
constexpr int QSTR = 44;   // k smem stride (packed bf16x2 words)
constexpr int VSTR = 88;   // v smem stride
constexpr int PST  = 68;   // P stride

constexpr int ATT_SMEM_WORDS =
    2 * KTK * QSTR + 2 * KTK * QSTR + 2 * KTK * VSTR + 4 * 16 * PST + 2 * QTQ + 2;

__global__ void __launch_bounds__(128, 2) attn_mma_kernel(
    const uint32_t* __restrict__ gqhi, const uint32_t* __restrict__ gqlo,
    const uint32_t* __restrict__ gkhi, const uint32_t* __restrict__ gklo,
    const uint32_t* __restrict__ gvtf, const int* __restrict__ cu,
    uint32_t* __restrict__ attn_tf)
{
    extern __shared__ uint32_t sm[];
    uint32_t* khiS = sm;
    uint32_t* kloS = khiS + 2 * KTK * QSTR;
    uint32_t* vS   = kloS + 2 * KTK * QSTR;
    uint32_t* pS   = vS + 2 * KTK * VSTR;
    int*      rs   = (int*)(pS + 4 * 16 * PST);
    int*      re   = rs + QTQ;
    int*      blk  = re + QTQ;

    const int h    = blockIdx.y;
    const int q0   = blockIdx.x * QTQ;
    const int tid  = threadIdx.x;
    const int w    = tid >> 5;
    const int lane = tid & 31;
    const int g    = lane >> 2;
    const int qd   = lane & 3;

    if (tid < QTQ) {
        const int n = q0 + tid;
        int lo = 0, hi = N_TOK;
        #pragma unroll
        for (int sgi = 0; sgi < NSEG; sgi++) {
            const int a = cu[sgi], b = cu[sgi + 1];
            if (n >= a && n < b) { lo = a; hi = b; }
        }
        rs[tid] = lo; re[tid] = hi;
    }
    __syncthreads();
    if (tid == 0) {
        int lo = rs[0], hi = re[0];
        #pragma unroll
        for (int r = 1; r < QTQ; r++) { lo = min(lo, rs[r]); hi = max(hi, re[r]); }
        blk[0] = lo; blk[1] = hi;
    }

    int wlo = N_TOK, whi = 0, wrs_max = 0, wre_min = N_TOK;
    #pragma unroll
    for (int r = 0; r < 16; r++) {
        const int a = rs[w * 16 + r], b = re[w * 16 + r];
        wlo = min(wlo, a); whi = max(whi, b);
        wrs_max = max(wrs_max, a); wre_min = min(wre_min, b);
    }
    const int rowA = w * 16 + g, rowB = rowA + 8;
    const int rsA = rs[rowA], reA = re[rowA];
    const int rsB = rs[rowB], reB = re[rowB];

    const size_t hb40 = (size_t)h * N_TOK * WPR;
    const size_t hb80 = (size_t)h * N_TOK * HK;
    uint32_t qh[5][4], ql[5][4];
    #pragma unroll
    for (int sl = 0; sl < 5; sl++) {
        const size_t bA = hb40 + (size_t)(q0 + rowA) * WPR + sl * 8;
        const size_t bB = hb40 + (size_t)(q0 + rowB) * WPR + sl * 8;
        qh[sl][0] = gqhi[bA + qd];     qh[sl][1] = gqhi[bB + qd];
        qh[sl][2] = gqhi[bA + 4 + qd]; qh[sl][3] = gqhi[bB + 4 + qd];
        ql[sl][0] = gqlo[bA + qd];     ql[sl][1] = gqlo[bB + qd];
        ql[sl][2] = gqlo[bA + 4 + qd]; ql[sl][3] = gqlo[bB + 4 + qd];
    }
    __syncthreads();
    const int lo = blk[0], hi = blk[1];

    auto stageKV = [&](int kc, int buf) {
        uint32_t* kh_ = khiS + buf * KTK * QSTR;
        uint32_t* kl_ = kloS + buf * KTK * QSTR;
        uint32_t* v_  = vS + buf * KTK * VSTR;
        #pragma unroll
        for (int it = 0; it < 5; it++) {
            const int i = it * 128 + tid;
            const int r = i / 10, c = (i % 10) * 4;
            const int m = kc + r;
            const uint32_t sz = (m < hi) ? 16u : 0u;
            const size_t go = hb40 + (size_t)min(m, hi - 1) * WPR + c;
            CP_ASYNC16Z(smem_addr(&kh_[r * QSTR + c]), &gkhi[go], sz);
            CP_ASYNC16Z(smem_addr(&kl_[r * QSTR + c]), &gklo[go], sz);
        }
        #pragma unroll
        for (int it = 0; it < 10; it++) {
            const int i = it * 128 + tid;
            const int r = i / 20, c = (i % 20) * 4;
            const int m = kc + r;
            const uint32_t sz = (m < hi) ? 16u : 0u;
            const size_t go = hb80 + (size_t)min(m, hi - 1) * HK + c;
            CP_ASYNC16Z(smem_addr(&v_[r * VSTR + c]), &gvtf[go], sz);
        }
        CP_COMMIT();
    };

    float miA = -1e30f, liA = 0.f, miB = -1e30f, liB = 0.f;
    float acc[10][4] = {};
    uint32_t* pw = pS + w * (16 * PST);

    const int T = (hi - lo + KTK - 1) / KTK;
    stageKV(lo, 0);

    for (int t = 0; t < T; t++) {
        const int kc  = lo + t * KTK;
        const int buf = t & 1;
        if (t + 1 < T) { stageKV(kc + KTK, buf ^ 1); CP_WAIT1(); }
        else           { CP_WAIT0(); }
        __syncthreads();

        if (!(kc + KTK <= wlo || kc >= whi)) {
            const uint32_t* kh_ = khiS + buf * KTK * QSTR;
            const uint32_t* kl_ = kloS + buf * KTK * QSTR;
            const uint32_t* v_  = vS + buf * KTK * VSTR;

            // ---- S = Q K^T (3x bf16 hi/lo), 16x64 strip per warp ----
            float s[8][4] = {};
            #pragma unroll
            for (int sl = 0; sl < 5; sl++) {
                const int base = sl * 8;
                #pragma unroll
                for (int nt = 0; nt < 8; nt++) {
                    const int kr = (nt * 8 + g) * QSTR + base;
                    uint32_t bh[2], bl[2];
                    bh[0] = kh_[kr + qd]; bh[1] = kh_[kr + 4 + qd];
                    bl[0] = kl_[kr + qd]; bl[1] = kl_[kr + 4 + qd];
                    mma_bf16(s[nt], qh[sl], bh);
                    mma_bf16(s[nt], qh[sl], bl);
                    mma_bf16(s[nt], ql[sl], bh);
                }
            }

            // ---- softmax: fast path interior / masked path at boundaries ----
            float mxA = -1e30f, mxB = -1e30f, sumA = 0.f, sumB = 0.f;
            float nmA, nmB;
            const bool full = (kc >= wrs_max) && (kc + KTK <= wre_min);
            if (full) {
                #pragma unroll
                for (int nt = 0; nt < 8; nt++) {
                    mxA = fmaxf(mxA, fmaxf(s[nt][0], s[nt][1]));
                    mxB = fmaxf(mxB, fmaxf(s[nt][2], s[nt][3]));
                }
                #pragma unroll
                for (int off = 1; off <= 2; off <<= 1) {
                    mxA = fmaxf(mxA, __shfl_xor_sync(0xffffffffu, mxA, off));
                    mxB = fmaxf(mxB, __shfl_xor_sync(0xffffffffu, mxB, off));
                }
                nmA = fmaxf(miA, mxA); nmB = fmaxf(miB, mxB);
                #pragma unroll
                for (int nt = 0; nt < 8; nt++) {
                    s[nt][0] = __expf(s[nt][0] - nmA);
                    s[nt][1] = __expf(s[nt][1] - nmA);
                    s[nt][2] = __expf(s[nt][2] - nmB);
                    s[nt][3] = __expf(s[nt][3] - nmB);
                    sumA += s[nt][0] + s[nt][1];
                    sumB += s[nt][2] + s[nt][3];
                }
            } else {
                #pragma unroll
                for (int nt = 0; nt < 8; nt++) {
                    const int c0 = kc + nt * 8 + 2 * qd;
                    const int c1 = c0 + 1;
                    mxA = fmaxf(mxA, fmaxf((c0 >= rsA && c0 < reA) ? s[nt][0] : -1e30f,
                                           (c1 >= rsA && c1 < reA) ? s[nt][1] : -1e30f));
                    mxB = fmaxf(mxB, fmaxf((c0 >= rsB && c0 < reB) ? s[nt][2] : -1e30f,
                                           (c1 >= rsB && c1 < reB) ? s[nt][3] : -1e30f));
                }
                #pragma unroll
                for (int off = 1; off <= 2; off <<= 1) {
                    mxA = fmaxf(mxA, __shfl_xor_sync(0xffffffffu, mxA, off));
                    mxB = fmaxf(mxB, __shfl_xor_sync(0xffffffffu, mxB, off));
                }
                nmA = fmaxf(miA, mxA); nmB = fmaxf(miB, mxB);
                #pragma unroll
                for (int nt = 0; nt < 8; nt++) {
                    const int c0 = kc + nt * 8 + 2 * qd;
                    const int c1 = c0 + 1;
                    s[nt][0] = (c0 >= rsA && c0 < reA) ? __expf(s[nt][0] - nmA) : 0.f;
                    s[nt][1] = (c1 >= rsA && c1 < reA) ? __expf(s[nt][1] - nmA) : 0.f;
                    s[nt][2] = (c0 >= rsB && c0 < reB) ? __expf(s[nt][2] - nmB) : 0.f;
                    s[nt][3] = (c1 >= rsB && c1 < reB) ? __expf(s[nt][3] - nmB) : 0.f;
                    sumA += s[nt][0] + s[nt][1];
                    sumB += s[nt][2] + s[nt][3];
                }
            }
            #pragma unroll
            for (int off = 1; off <= 2; off <<= 1) {
                sumA += __shfl_xor_sync(0xffffffffu, sumA, off);
                sumB += __shfl_xor_sync(0xffffffffu, sumB, off);
            }

            // ---- exact no-op rescale skip: cr == 1.0 iff nm == mi ----
            if (nmA != miA || nmB != miB) {
                const float crA = __expf(miA - nmA);
                const float crB = __expf(miB - nmB);
                liA = liA * crA; liB = liB * crB;
                #pragma unroll
                for (int nt = 0; nt < 10; nt++) {
                    acc[nt][0] *= crA; acc[nt][1] *= crA;
                    acc[nt][2] *= crB; acc[nt][3] *= crB;
                }
                miA = nmA; miB = nmB;
            }
            liA += sumA; liB += sumB;

            // ---- P -> warp-private smem (tf32), then PV (tf32) ----
            #pragma unroll
            for (int nt = 0; nt < 8; nt++) {
                const int cb = nt * 8 + 2 * qd;
                uint2 pa, pb;
                pa.x = f2tf32(s[nt][0]); pa.y = f2tf32(s[nt][1]);
                pb.x = f2tf32(s[nt][2]); pb.y = f2tf32(s[nt][3]);
                *reinterpret_cast<uint2*>(&pw[g * PST + cb])       = pa;
                *reinterpret_cast<uint2*>(&pw[(g + 8) * PST + cb]) = pb;
            }
            __syncwarp();

            #pragma unroll
            for (int k8 = 0; k8 < KTK; k8 += 8) {
                uint32_t a[4];
                a[0] = pw[g * PST + k8 + qd];
                a[1] = pw[(g + 8) * PST + k8 + qd];
                a[2] = pw[g * PST + k8 + 4 + qd];
                a[3] = pw[(g + 8) * PST + k8 + 4 + qd];
                #pragma unroll
                for (int nt = 0; nt < 10; nt++) {
                    uint32_t b[2];
                    b[0] = v_[(k8 + qd) * VSTR + nt * 8 + g];
                    b[1] = v_[(k8 + 4 + qd) * VSTR + nt * 8 + g];
                    mma_tf32(acc[nt], a, b);
                }
            }
            __syncwarp();
        }
        __syncthreads();
    }

    const float invA = 1.f / liA, invB = 1.f / liB;
    uint32_t* dA = attn_tf + (size_t)(q0 + rowA) * D + h * HK;
    uint32_t* dB = attn_tf + (size_t)(q0 + rowB) * D + h * HK;
    #pragma unroll
    for (int nt = 0; nt < 10; nt++) {
        const int col = nt * 8 + 2 * qd;
        dA[col]     = f2tf32(acc[nt][0] * invA);
        dA[col + 1] = f2tf32(acc[nt][1] * invA);
        dB[col]     = f2tf32(acc[nt][2] * invB);
        dB[col + 1] = f2tf32(acc[nt][3] * invB);
    }
}

// ---------------- launch ----------------
extern "C" void kernel_launch(void* const* d_in, const int* in_sizes, int n_in,
                              void* d_out, int out_size)
{
    const float* hidden = (const float*)d_in[0];
    const int*   cu     = (const int*)  d_in[1];
    const float* cosNK  = (const float*)d_in[2];
    const float* sinNK  = (const float*)d_in[3];
    const float* qkv_w  = (const float*)d_in[4];
    const float* qkv_b  = (const float*)d_in[5];
    const float* proj_w = (const float*)d_in[6];
    const float* proj_b = (const float*)d_in[7];
    float* out = (float*)d_out;

    float *qkv;
    uint32_t *hidtf, *qkvwtf, *projwtf, *qhib, *qlob, *khib, *klob, *vtf, *attntf;
    cudaGetSymbolAddress((void**)&hidtf,  g_hid_tf);
    cudaGetSymbolAddress((void**)&qkvwtf, g_qkvw_tf);
    cudaGetSymbolAddress((void**)&projwtf,g_projw_tf);
    cudaGetSymbolAddress((void**)&qkv,    g_qkv);
    cudaGetSymbolAddress((void**)&qhib,   g_qhib);
    cudaGetSymbolAddress((void**)&qlob,   g_qlob);
    cudaGetSymbolAddress((void**)&khib,   g_khib);
    cudaGetSymbolAddress((void**)&klob,   g_klob);
    cudaGetSymbolAddress((void**)&vtf,    g_vtf);
    cudaGetSymbolAddress((void**)&attntf, g_attn_tf);

    const size_t attn_smem = ATT_SMEM_WORDS * sizeof(uint32_t);
    static bool attr_done = false;
    if (!attr_done) {
        cudaFuncSetAttribute(tgemm128_kernel<3 * D, D>,
                             cudaFuncAttributeMaxDynamicSharedMemorySize, GEMM_SMEM1);
        cudaFuncSetAttribute(tgemm256_kernel<D, D>,
                             cudaFuncAttributeMaxDynamicSharedMemorySize, GEMM_SMEM2);
        cudaFuncSetAttribute(attn_mma_kernel,
                             cudaFuncAttributeMaxDynamicSharedMemorySize, (int)attn_smem);
        attr_done = true;
    }

    // 0) merged converts
    convert_all_kernel<<<(CVT_TOT + 255) / 256, 256>>>(
        hidden, qkv_w, proj_w, hidtf, qkvwtf, projwtf);

    // 1) QKV GEMM + bias
    tgemm128_kernel<3 * D, D><<<dim3((3 * D) / 128, N_TOK / 128), 256, GEMM_SMEM1>>>(
        hidtf, qkvwtf, qkv_b, qkv);

    // 2) RoPE + split
    rope_split_kernel<<<(N_TOK * H * WPR + 255) / 256, 256>>>(
        qkv, cosNK, sinNK, qhib, qlob, khib, klob, vtf);

    // 3) attention (QTQ=64, KTK=64, fast path + rescale skip)
    attn_mma_kernel<<<dim3(N_TOK / QTQ, H), 128, attn_smem>>>(
        qhib, qlob, khib, klob, vtf, cu, attntf);

    // 4) projection GEMM + bias -> d_out
    tgemm256_kernel<D, D><<<dim3(D / 256, N_TOK / 128), 256, GEMM_SMEM2>>>(
        attntf, projwtf, proj_b, out);
}

// round 17
// speedup vs baseline: 1.0534x; 1.0043x over previous
#include <cuda_runtime.h>
#include <cuda_bf16.h>
#include <cstdint>

// Problem constants
constexpr int N_TOK = 3072;
constexpr int D     = 1280;
constexpr int H     = 16;
constexpr int HK    = 80;     // head dim
constexpr int WPR   = HK / 2; // packed bf16 words per row (40)
constexpr int HWPR  = WPR / 2;// 20: pair-words handled per thread group
constexpr int NSEG  = 8;
constexpr float SCALE = 0.111803398874989485f; // 80^-0.5

// ---------------- scratch ----------------
__device__ uint32_t g_hid_tf[N_TOK * D];        // tf32 of hidden
__device__ uint32_t g_qkvw_tf[D * 3 * D];       // tf32 of qkv_w
__device__ uint32_t g_projw_tf[D * D];          // tf32 of proj_w
__device__ float    g_qkv[N_TOK * 3 * D];       // [N][3][H][K] fp32
__device__ uint32_t g_qhib[H * N_TOK * WPR];    // bf16x2 hi of SCALE*rope(q)
__device__ uint32_t g_qlob[H * N_TOK * WPR];
__device__ uint32_t g_khib[H * N_TOK * WPR];
__device__ uint32_t g_klob[H * N_TOK * WPR];
__device__ uint32_t g_vtf[H * N_TOK * HK];      // tf32 v
__device__ uint32_t g_attn_tf[N_TOK * D];       // tf32 attn out [N][H*K]

// ---------------- helpers ----------------
__device__ __forceinline__ uint32_t f2tf32(float x) {
    uint32_t r;
    asm("cvt.rna.tf32.f32 %0, %1;" : "=r"(r) : "f"(x));
    return r;
}
__device__ __forceinline__ void mma_tf32(float c[4], const uint32_t a[4], const uint32_t b[2]) {
    asm volatile(
        "mma.sync.aligned.m16n8k8.row.col.f32.tf32.tf32.f32 "
        "{%0,%1,%2,%3}, {%4,%5,%6,%7}, {%8,%9}, {%0,%1,%2,%3};"
        : "+f"(c[0]), "+f"(c[1]), "+f"(c[2]), "+f"(c[3])
        : "r"(a[0]), "r"(a[1]), "r"(a[2]), "r"(a[3]), "r"(b[0]), "r"(b[1]));
}
__device__ __forceinline__ void mma_bf16(float c[4], const uint32_t a[4], const uint32_t b[2]) {
    asm volatile(
        "mma.sync.aligned.m16n8k16.row.col.f32.bf16.bf16.f32 "
        "{%0,%1,%2,%3}, {%4,%5,%6,%7}, {%8,%9}, {%0,%1,%2,%3};"
        : "+f"(c[0]), "+f"(c[1]), "+f"(c[2]), "+f"(c[3])
        : "r"(a[0]), "r"(a[1]), "r"(a[2]), "r"(a[3]), "r"(b[0]), "r"(b[1]));
}
__device__ __forceinline__ uint32_t bf16bits(float x) {
    const __nv_bfloat16 b = __float2bfloat16(x);
    return (uint32_t)*reinterpret_cast<const uint16_t*>(&b);
}
__device__ __forceinline__ float bf16val(uint32_t bits) {
    const uint16_t u = (uint16_t)bits;
    return __bfloat162float(*reinterpret_cast<const __nv_bfloat16*>(&u));
}
__device__ __forceinline__ uint32_t smem_addr(const void* p) {
    return (uint32_t)__cvta_generic_to_shared(p);
}
#define CP_ASYNC16(dst, src) \
    asm volatile("cp.async.cg.shared.global [%0], [%1], 16;" :: "r"(dst), "l"(src))
#define CP_ASYNC16Z(dst, src, sz) \
    asm volatile("cp.async.cg.shared.global [%0], [%1], 16, %2;" :: "r"(dst), "l"(src), "r"(sz))
#define CP_COMMIT() asm volatile("cp.async.commit_group;")
#define CP_WAIT1()  asm volatile("cp.async.wait_group 1;")
#define CP_WAIT0()  asm volatile("cp.async.wait_group 0;")

// ---------------- merged f32 -> tf32 convert (hidden + qkv_w + proj_w) ----------------
constexpr int CVT_N1 = N_TOK * D / 4;
constexpr int CVT_N2 = D * 3 * D / 4;
constexpr int CVT_N3 = D * D / 4;
constexpr int CVT_TOT = CVT_N1 + CVT_N2 + CVT_N3;

__global__ void __launch_bounds__(256) convert_all_kernel(
    const float* __restrict__ hid, const float* __restrict__ qw,
    const float* __restrict__ pw,
    uint32_t* __restrict__ hidtf, uint32_t* __restrict__ qwtf,
    uint32_t* __restrict__ pwtf)
{
    const int i = blockIdx.x * blockDim.x + threadIdx.x;
    if (i >= CVT_TOT) return;
    const float* s;
    uint32_t* d;
    int j = i;
    if (j < CVT_N1)            { s = hid; d = hidtf; }
    else if ((j -= CVT_N1) < CVT_N2) { s = qw; d = qwtf; }
    else                       { j -= CVT_N2; s = pw; d = pwtf; }
    const float4 x = reinterpret_cast<const float4*>(s)[j];
    uint4 y;
    y.x = f2tf32(x.x); y.y = f2tf32(x.y); y.z = f2tf32(x.z); y.w = f2tf32(x.w);
    reinterpret_cast<uint4*>(d)[j] = y;
}

// ---------------- tf32 GEMM v128: BM=128, BN=128, 3-stage cp.async, 1 barrier/tile ----------------
constexpr int ASTR = 36;
constexpr int BSTR1 = 136;
constexpr int A_WORDS = 128 * ASTR;
constexpr int B_WORDS1 = 32 * BSTR1;
constexpr int STAGE1 = A_WORDS + B_WORDS1;
constexpr int GEMM_SMEM1 = 3 * STAGE1 * 4;

template<int NN, int KD>
__global__ void __launch_bounds__(256) tgemm128_kernel(
    const uint32_t* __restrict__ A, const uint32_t* __restrict__ B,
    const float* __restrict__ bias, float* __restrict__ C)
{
    extern __shared__ uint32_t smem[];

    const int tid  = threadIdx.x;
    const int lane = tid & 31;
    const int w    = tid >> 5;
    const int g    = lane >> 2;
    const int qd   = lane & 3;
    const int wm   = w >> 2;
    const int wn   = w & 3;
    const int bm   = blockIdx.y * 128;
    const int bn   = blockIdx.x * 128;

    const int ar = tid >> 1;
    const int ah = (tid & 1) * 16;
    const int br = tid >> 3;
    const int bc = tid & 7;

    auto issue = [&](int kt) {
        const int k0 = kt * 32;
        uint32_t* as = smem + (kt % 3) * STAGE1;
        uint32_t* bs = as + A_WORDS;
        #pragma unroll
        for (int i = 0; i < 4; i++) {
            const uint32_t dst = smem_addr(&as[ar * ASTR + ah + i * 4]);
            CP_ASYNC16(dst, &A[(size_t)(bm + ar) * KD + k0 + ah + i * 4]);
        }
        #pragma unroll
        for (int i = 0; i < 4; i++) {
            const int col = (bc + 8 * i) * 4;
            const uint32_t dst = smem_addr(&bs[br * BSTR1 + col]);
            CP_ASYNC16(dst, &B[(size_t)(k0 + br) * NN + bn + col]);
        }
        CP_COMMIT();
    };

    float acc[4][4][4] = {};

    issue(0);
    issue(1);

    constexpr int KT = KD / 32;
    for (int kt = 0; kt < KT; kt++) {
        CP_WAIT1();
        __syncthreads();
        if (kt + 2 < KT) issue(kt + 2);

        const uint32_t* as = smem + (kt % 3) * STAGE1;
        const uint32_t* bs = as + A_WORDS;

        #pragma unroll
        for (int kk = 0; kk < 32; kk += 8) {
            uint32_t af[4][4], bf[4][2];
            #pragma unroll
            for (int mi = 0; mi < 4; mi++) {
                const int r0 = (wm * 64 + mi * 16 + g) * ASTR;
                af[mi][0] = as[r0 + kk + qd];
                af[mi][1] = as[r0 + 8 * ASTR + kk + qd];
                af[mi][2] = as[r0 + kk + 4 + qd];
                af[mi][3] = as[r0 + 8 * ASTR + kk + 4 + qd];
            }
            #pragma unroll
            for (int ni = 0; ni < 4; ni++) {
                const int c0 = wn * 32 + ni * 8 + g;
                bf[ni][0] = bs[(kk + qd) * BSTR1 + c0];
                bf[ni][1] = bs[(kk + 4 + qd) * BSTR1 + c0];
            }
            #pragma unroll
            for (int mi = 0; mi < 4; mi++)
                #pragma unroll
                for (int ni = 0; ni < 4; ni++)
                    mma_tf32(acc[mi][ni], af[mi], bf[ni]);
        }
        // no trailing barrier: buffer kt%3 is next written by issue(kt+3) at
        // iteration kt+1, which is AFTER that iteration's CP_WAIT1+__syncthreads.
    }

    #pragma unroll
    for (int mi = 0; mi < 4; mi++) {
        const int row = bm + wm * 64 + mi * 16 + g;
        #pragma unroll
        for (int ni = 0; ni < 4; ni++) {
            const int col = bn + wn * 32 + ni * 8 + 2 * qd;
            const float2 bb = *reinterpret_cast<const float2*>(&bias[col]);
            float2 o0, o1;
            o0.x = acc[mi][ni][0] + bb.x; o0.y = acc[mi][ni][1] + bb.y;
            o1.x = acc[mi][ni][2] + bb.x; o1.y = acc[mi][ni][3] + bb.y;
            *reinterpret_cast<float2*>(&C[(size_t)row * NN + col]) = o0;
            *reinterpret_cast<float2*>(&C[(size_t)(row + 8) * NN + col]) = o1;
        }
    }
}

// ---------------- tf32 GEMM v256: BM=128, BN=256 (single-wave proj), 1 barrier/tile ----------------
constexpr int BSTR2 = 264;
constexpr int B_WORDS2 = 32 * BSTR2;
constexpr int STAGE2 = A_WORDS + B_WORDS2;
constexpr int GEMM_SMEM2 = 3 * STAGE2 * 4;

template<int NN, int KD>
__global__ void __launch_bounds__(256) tgemm256_kernel(
    const uint32_t* __restrict__ A, const uint32_t* __restrict__ B,
    const float* __restrict__ bias, float* __restrict__ C)
{
    extern __shared__ uint32_t smem[];

    const int tid  = threadIdx.x;
    const int lane = tid & 31;
    const int w    = tid >> 5;
    const int g    = lane >> 2;
    const int qd   = lane & 3;
    const int wm   = w >> 2;
    const int wn   = w & 3;
    const int bm   = blockIdx.y * 128;
    const int bn   = blockIdx.x * 256;

    const int ar = tid >> 1;
    const int ah = (tid & 1) * 16;
    const int br = tid >> 3;
    const int bc = tid & 7;

    auto issue = [&](int kt) {
        const int k0 = kt * 32;
        uint32_t* as = smem + (kt % 3) * STAGE2;
        uint32_t* bs = as + A_WORDS;
        #pragma unroll
        for (int i = 0; i < 4; i++) {
            const uint32_t dst = smem_addr(&as[ar * ASTR + ah + i * 4]);
            CP_ASYNC16(dst, &A[(size_t)(bm + ar) * KD + k0 + ah + i * 4]);
        }
        #pragma unroll
        for (int i = 0; i < 8; i++) {
            const int col = (bc + 8 * i) * 4;
            const uint32_t dst = smem_addr(&bs[br * BSTR2 + col]);
            CP_ASYNC16(dst, &B[(size_t)(k0 + br) * NN + bn + col]);
        }
        CP_COMMIT();
    };

    float acc[4][8][4] = {};

    issue(0);
    issue(1);

    constexpr int KT = KD / 32;
    for (int kt = 0; kt < KT; kt++) {
        CP_WAIT1();
        __syncthreads();
        if (kt + 2 < KT) issue(kt + 2);

        const uint32_t* as = smem + (kt % 3) * STAGE2;
        const uint32_t* bs = as + A_WORDS;

        #pragma unroll
        for (int kk = 0; kk < 32; kk += 8) {
            uint32_t af[4][4], bf[8][2];
            #pragma unroll
            for (int mi = 0; mi < 4; mi++) {
                const int r0 = (wm * 64 + mi * 16 + g) * ASTR;
                af[mi][0] = as[r0 + kk + qd];
                af[mi][1] = as[r0 + 8 * ASTR + kk + qd];
                af[mi][2] = as[r0 + kk + 4 + qd];
                af[mi][3] = as[r0 + 8 * ASTR + kk + 4 + qd];
            }
            #pragma unroll
            for (int ni = 0; ni < 8; ni++) {
                const int c0 = wn * 64 + ni * 8 + g;
                bf[ni][0] = bs[(kk + qd) * BSTR2 + c0];
                bf[ni][1] = bs[(kk + 4 + qd) * BSTR2 + c0];
            }
            #pragma unroll
            for (int mi = 0; mi < 4; mi++)
                #pragma unroll
                for (int ni = 0; ni < 8; ni++)
                    mma_tf32(acc[mi][ni], af[mi], bf[ni]);
        }
        // no trailing barrier (same 3-stage argument as tgemm128)
    }

    #pragma unroll
    for (int mi = 0; mi < 4; mi++) {
        const int row = bm + wm * 64 + mi * 16 + g;
        #pragma unroll
        for (int ni = 0; ni < 8; ni++) {
            const int col = bn + wn * 64 + ni * 8 + 2 * qd;
            const float2 bb = *reinterpret_cast<const float2*>(&bias[col]);
            float2 o0, o1;
            o0.x = acc[mi][ni][0] + bb.x; o0.y = acc[mi][ni][1] + bb.y;
            o1.x = acc[mi][ni][2] + bb.x; o1.y = acc[mi][ni][3] + bb.y;
            *reinterpret_cast<float2*>(&C[(size_t)row * NN + col]) = o0;
            *reinterpret_cast<float2*>(&C[(size_t)(row + 8) * NN + col]) = o1;
        }
    }
}

// ---------------- RoPE (pair-owning threads, float2 loads) ----------------
// Thread owns packed words wd and wd+20 of one (n,h): elements {2wd,2wd+1}
// and {2wd+40, 2wd+41}. Each q/k/v element loaded exactly once (float2).
__global__ void __launch_bounds__(256) rope_split_kernel(
    const float* __restrict__ qkv, const float* __restrict__ cosNK,
    const float* __restrict__ sinNK,
    uint32_t* __restrict__ qhib, uint32_t* __restrict__ qlob,
    uint32_t* __restrict__ khib, uint32_t* __restrict__ klob,
    uint32_t* __restrict__ vtf)
{
    const int idx = blockIdx.x * blockDim.x + threadIdx.x;
    if (idx >= N_TOK * H * HWPR) return;
    const int wd = idx % HWPR;            // 0..19
    const int h  = (idx / HWPR) % H;
    const int n  = idx / (HWPR * H);

    const float* base = qkv + (size_t)n * 3 * H * HK + h * HK + 2 * wd;

    // element loads (lo = positions 2wd,2wd+1 ; hi = +40)
    const float2 qL = *reinterpret_cast<const float2*>(base);
    const float2 qH = *reinterpret_cast<const float2*>(base + HK / 2);
    const float2 kL = *reinterpret_cast<const float2*>(base + H * HK);
    const float2 kH = *reinterpret_cast<const float2*>(base + H * HK + HK / 2);
    const float2 vL = *reinterpret_cast<const float2*>(base + 2 * H * HK);
    const float2 vH = *reinterpret_cast<const float2*>(base + 2 * H * HK + HK / 2);

    const float2 cL = *reinterpret_cast<const float2*>(&cosNK[n * HK + 2 * wd]);
    const float2 cH = *reinterpret_cast<const float2*>(&cosNK[n * HK + 2 * wd + HK / 2]);
    const float2 sL = *reinterpret_cast<const float2*>(&sinNK[n * HK + 2 * wd]);
    const float2 sH = *reinterpret_cast<const float2*>(&sinNK[n * HK + 2 * wd + HK / 2]);

    // rope: out[kk] = in[kk]*c[kk] - in[kk+40]*s[kk]   (kk < 40)
    //       out[kk+40] = in[kk+40]*c[kk+40] + in[kk]*s[kk+40]
    float qrL[2], qrH[2], krL[2], krH[2];
    qrL[0] = (qL.x * cL.x + -1.f * qH.x * sL.x) * SCALE;
    qrL[1] = (qL.y * cL.y + -1.f * qH.y * sL.y) * SCALE;
    qrH[0] = (qH.x * cH.x + qL.x * sH.x) * SCALE;
    qrH[1] = (qH.y * cH.y + qL.y * sH.y) * SCALE;
    krL[0] = kL.x * cL.x + -1.f * kH.x * sL.x;
    krL[1] = kL.y * cL.y + -1.f * kH.y * sL.y;
    krH[0] = kH.x * cH.x + kL.x * sH.x;
    krH[1] = kH.y * cH.y + kL.y * sH.y;

    auto packhl = [](const float v0, const float v1, uint32_t& hi, uint32_t& lo) {
        const uint32_t h0 = bf16bits(v0), h1 = bf16bits(v1);
        hi = h0 | (h1 << 16);
        lo = bf16bits(v0 - bf16val(h0)) | (bf16bits(v1 - bf16val(h1)) << 16);
    };

    uint32_t qhl, qll, qhh, qlh, khl, kll, khh, klh;
    packhl(qrL[0], qrL[1], qhl, qll);
    packhl(qrH[0], qrH[1], qhh, qlh);
    packhl(krL[0], krL[1], khl, kll);
    packhl(krH[0], krH[1], khh, klh);

    const size_t owL = (size_t)h * N_TOK * WPR + (size_t)n * WPR + wd;
    const size_t owH = owL + HWPR;
    qhib[owL] = qhl; qhib[owH] = qhh;
    qlob[owL] = qll; qlob[owH] = qlh;
    khib[owL] = khl; khib[owH] = khh;
    klob[owL] = kll; klob[owH] = klh;

    const size_t ov = (size_t)h * N_TOK * HK + (size_t)n * HK + 2 * wd;
    uint2 v0, v1;
    v0.x = f2tf32(vL.x); v0.y = f2tf32(vL.y);
    v1.x = f2tf32(vH.x); v1.y = f2tf32(vH.y);
    *reinterpret_cast<uint2*>(&vtf[ov])          = v0;
    *reinterpret_cast<uint2*>(&vtf[ov + HK / 2]) = v1;
}

// ---------------- mma flash attention: QTQ=64, KTK=64, fast path + rescale skip ----------------
constexpr int QTQ  = 64;
constexpr int KTK  = 64;
constexpr int QSTR = 44;   // k smem stride (packed bf16x2 words)
constexpr int VSTR = 88;   // v smem stride
constexpr int PST  = 68;   // P stride

constexpr int ATT_SMEM_WORDS =
    2 * KTK * QSTR + 2 * KTK * QSTR + 2 * KTK * VSTR + 4 * 16 * PST + 2 * QTQ + 2;

__global__ void __launch_bounds__(128, 2) attn_mma_kernel(
    const uint32_t* __restrict__ gqhi, const uint32_t* __restrict__ gqlo,
    const uint32_t* __restrict__ gkhi, const uint32_t* __restrict__ gklo,
    const uint32_t* __restrict__ gvtf, const int* __restrict__ cu,
    uint32_t* __restrict__ attn_tf)
{
    extern __shared__ uint32_t sm[];
    uint32_t* khiS = sm;
    uint32_t* kloS = khiS + 2 * KTK * QSTR;
    uint32_t* vS   = kloS + 2 * KTK * QSTR;
    uint32_t* pS   = vS + 2 * KTK * VSTR;
    int*      rs   = (int*)(pS + 4 * 16 * PST);
    int*      re   = rs + QTQ;
    int*      blk  = re + QTQ;

    const int h    = blockIdx.y;
    const int q0   = blockIdx.x * QTQ;
    const int tid  = threadIdx.x;
    const int w    = tid >> 5;
    const int lane = tid & 31;
    const int g    = lane >> 2;
    const int qd   = lane & 3;

    if (tid < QTQ) {
        const int n = q0 + tid;
        int lo = 0, hi = N_TOK;
        #pragma unroll
        for (int sgi = 0; sgi < NSEG; sgi++) {
            const int a = cu[sgi], b = cu[sgi + 1];
            if (n >= a && n < b) { lo = a; hi = b; }
        }
        rs[tid] = lo; re[tid] = hi;
    }
    __syncthreads();
    if (tid == 0) {
        int lo = rs[0], hi = re[0];
        #pragma unroll
        for (int r = 1; r < QTQ; r++) { lo = min(lo, rs[r]); hi = max(hi, re[r]); }
        blk[0] = lo; blk[1] = hi;
    }

    int wlo = N_TOK, whi = 0, wrs_max = 0, wre_min = N_TOK;
    #pragma unroll
    for (int r = 0; r < 16; r++) {
        const int a = rs[w * 16 + r], b = re[w * 16 + r];
        wlo = min(wlo, a); whi = max(whi, b);
        wrs_max = max(wrs_max, a); wre_min = min(wre_min, b);
    }
    const int rowA = w * 16 + g, rowB = rowA + 8;
    const int rsA = rs[rowA], reA = re[rowA];
    const int rsB = rs[rowB], reB = re[rowB];

    const size_t hb40 = (size_t)h * N_TOK * WPR;
    const size_t hb80 = (size_t)h * N_TOK * HK;
    uint32_t qh[5][4], ql[5][4];
    #pragma unroll
    for (int sl = 0; sl < 5; sl++) {
        const size_t bA = hb40 + (size_t)(q0 + rowA) * WPR + sl * 8;
        const size_t bB = hb40 + (size_t)(q0 + rowB) * WPR + sl * 8;
        qh[sl][0] = gqhi[bA + qd];     qh[sl][1] = gqhi[bB + qd];
        qh[sl][2] = gqhi[bA + 4 + qd]; qh[sl][3] = gqhi[bB + 4 + qd];
        ql[sl][0] = gqlo[bA + qd];     ql[sl][1] = gqlo[bB + qd];
        ql[sl][2] = gqlo[bA + 4 + qd]; ql[sl][3] = gqlo[bB + 4 + qd];
    }
    __syncthreads();
    const int lo = blk[0], hi = blk[1];

    auto stageKV = [&](int kc, int buf) {
        uint32_t* kh_ = khiS + buf * KTK * QSTR;
        uint32_t* kl_ = kloS + buf * KTK * QSTR;
        uint32_t* v_  = vS + buf * KTK * VSTR;
        #pragma unroll
        for (int it = 0; it < 5; it++) {
            const int i = it * 128 + tid;
            const int r = i / 10, c = (i % 10) * 4;
            const int m = kc + r;
            const uint32_t sz = (m < hi) ? 16u : 0u;
            const size_t go = hb40 + (size_t)min(m, hi - 1) * WPR + c;
            CP_ASYNC16Z(smem_addr(&kh_[r * QSTR + c]), &gkhi[go], sz);
            CP_ASYNC16Z(smem_addr(&kl_[r * QSTR + c]), &gklo[go], sz);
        }
        #pragma unroll
        for (int it = 0; it < 10; it++) {
            const int i = it * 128 + tid;
            const int r = i / 20, c = (i % 20) * 4;
            const int m = kc + r;
            const uint32_t sz = (m < hi) ? 16u : 0u;
            const size_t go = hb80 + (size_t)min(m, hi - 1) * HK + c;
            CP_ASYNC16Z(smem_addr(&v_[r * VSTR + c]), &gvtf[go], sz);
        }
        CP_COMMIT();
    };

    float miA = -1e30f, liA = 0.f, miB = -1e30f, liB = 0.f;
    float acc[10][4] = {};
    uint32_t* pw = pS + w * (16 * PST);

    const int T = (hi - lo + KTK - 1) / KTK;
    stageKV(lo, 0);

    for (int t = 0; t < T; t++) {
        const int kc  = lo + t * KTK;
        const int buf = t & 1;
        if (t + 1 < T) { stageKV(kc + KTK, buf ^ 1); CP_WAIT1(); }
        else           { CP_WAIT0(); }
        __syncthreads();

        if (!(kc + KTK <= wlo || kc >= whi)) {
            const uint32_t* kh_ = khiS + buf * KTK * QSTR;
            const uint32_t* kl_ = kloS + buf * KTK * QSTR;
            const uint32_t* v_  = vS + buf * KTK * VSTR;

            // ---- S = Q K^T (3x bf16 hi/lo), 16x64 strip per warp ----
            float s[8][4] = {};
            #pragma unroll
            for (int sl = 0; sl < 5; sl++) {
                const int base = sl * 8;
                #pragma unroll
                for (int nt = 0; nt < 8; nt++) {
                    const int kr = (nt * 8 + g) * QSTR + base;
                    uint32_t bh[2], bl[2];
                    bh[0] = kh_[kr + qd]; bh[1] = kh_[kr + 4 + qd];
                    bl[0] = kl_[kr + qd]; bl[1] = kl_[kr + 4 + qd];
                    mma_bf16(s[nt], qh[sl], bh);
                    mma_bf16(s[nt], qh[sl], bl);
                    mma_bf16(s[nt], ql[sl], bh);
                }
            }

            // ---- softmax: fast path interior / masked path at boundaries ----
            float mxA = -1e30f, mxB = -1e30f, sumA = 0.f, sumB = 0.f;
            float nmA, nmB;
            const bool full = (kc >= wrs_max) && (kc + KTK <= wre_min);
            if (full) {
                #pragma unroll
                for (int nt = 0; nt < 8; nt++) {
                    mxA = fmaxf(mxA, fmaxf(s[nt][0], s[nt][1]));
                    mxB = fmaxf(mxB, fmaxf(s[nt][2], s[nt][3]));
                }
                #pragma unroll
                for (int off = 1; off <= 2; off <<= 1) {
                    mxA = fmaxf(mxA, __shfl_xor_sync(0xffffffffu, mxA, off));
                    mxB = fmaxf(mxB, __shfl_xor_sync(0xffffffffu, mxB, off));
                }
                nmA = fmaxf(miA, mxA); nmB = fmaxf(miB, mxB);
                #pragma unroll
                for (int nt = 0; nt < 8; nt++) {
                    s[nt][0] = __expf(s[nt][0] - nmA);
                    s[nt][1] = __expf(s[nt][1] - nmA);
                    s[nt][2] = __expf(s[nt][2] - nmB);
                    s[nt][3] = __expf(s[nt][3] - nmB);
                    sumA += s[nt][0] + s[nt][1];
                    sumB += s[nt][2] + s[nt][3];
                }
            } else {
                #pragma unroll
                for (int nt = 0; nt < 8; nt++) {
                    const int c0 = kc + nt * 8 + 2 * qd;
                    const int c1 = c0 + 1;
                    mxA = fmaxf(mxA, fmaxf((c0 >= rsA && c0 < reA) ? s[nt][0] : -1e30f,
                                           (c1 >= rsA && c1 < reA) ? s[nt][1] : -1e30f));
                    mxB = fmaxf(mxB, fmaxf((c0 >= rsB && c0 < reB) ? s[nt][2] : -1e30f,
                                           (c1 >= rsB && c1 < reB) ? s[nt][3] : -1e30f));
                }
                #pragma unroll
                for (int off = 1; off <= 2; off <<= 1) {
                    mxA = fmaxf(mxA, __shfl_xor_sync(0xffffffffu, mxA, off));
                    mxB = fmaxf(mxB, __shfl_xor_sync(0xffffffffu, mxB, off));
                }
                nmA = fmaxf(miA, mxA); nmB = fmaxf(miB, mxB);
                #pragma unroll
                for (int nt = 0; nt < 8; nt++) {
                    const int c0 = kc + nt * 8 + 2 * qd;
                    const int c1 = c0 + 1;
                    s[nt][0] = (c0 >= rsA && c0 < reA) ? __expf(s[nt][0] - nmA) : 0.f;
                    s[nt][1] = (c1 >= rsA && c1 < reA) ? __expf(s[nt][1] - nmA) : 0.f;
                    s[nt][2] = (c0 >= rsB && c0 < reB) ? __expf(s[nt][2] - nmB) : 0.f;
                    s[nt][3] = (c1 >= rsB && c1 < reB) ? __expf(s[nt][3] - nmB) : 0.f;
                    sumA += s[nt][0] + s[nt][1];
                    sumB += s[nt][2] + s[nt][3];
                }
            }
            #pragma unroll
            for (int off = 1; off <= 2; off <<= 1) {
                sumA += __shfl_xor_sync(0xffffffffu, sumA, off);
                sumB += __shfl_xor_sync(0xffffffffu, sumB, off);
            }

            // ---- exact no-op rescale skip: cr == 1.0 iff nm == mi ----
            if (nmA != miA || nmB != miB) {
                const float crA = __expf(miA - nmA);
                const float crB = __expf(miB - nmB);
                liA = liA * crA; liB = liB * crB;
                #pragma unroll
                for (int nt = 0; nt < 10; nt++) {
                    acc[nt][0] *= crA; acc[nt][1] *= crA;
                    acc[nt][2] *= crB; acc[nt][3] *= crB;
                }
                miA = nmA; miB = nmB;
            }
            liA += sumA; liB += sumB;

            // ---- P -> warp-private smem (tf32), then PV (tf32) ----
            #pragma unroll
            for (int nt = 0; nt < 8; nt++) {
                const int cb = nt * 8 + 2 * qd;
                uint2 pa, pb;
                pa.x = f2tf32(s[nt][0]); pa.y = f2tf32(s[nt][1]);
                pb.x = f2tf32(s[nt][2]); pb.y = f2tf32(s[nt][3]);
                *reinterpret_cast<uint2*>(&pw[g * PST + cb])       = pa;
                *reinterpret_cast<uint2*>(&pw[(g + 8) * PST + cb]) = pb;
            }
            __syncwarp();

            #pragma unroll
            for (int k8 = 0; k8 < KTK; k8 += 8) {
                uint32_t a[4];
                a[0] = pw[g * PST + k8 + qd];
                a[1] = pw[(g + 8) * PST + k8 + qd];
                a[2] = pw[g * PST + k8 + 4 + qd];
                a[3] = pw[(g + 8) * PST + k8 + 4 + qd];
                #pragma unroll
                for (int nt = 0; nt < 10; nt++) {
                    uint32_t b[2];
                    b[0] = v_[(k8 + qd) * VSTR + nt * 8 + g];
                    b[1] = v_[(k8 + 4 + qd) * VSTR + nt * 8 + g];
                    mma_tf32(acc[nt], a, b);
                }
            }
            __syncwarp();
        }
        __syncthreads();
    }

    // ---- epilogue: normalize, vectorized uint2 stores ----
    const float invA = 1.f / liA, invB = 1.f / liB;
    uint32_t* dA = attn_tf + (size_t)(q0 + rowA) * D + h * HK;
    uint32_t* dB = attn_tf + (size_t)(q0 + rowB) * D + h * HK;
    #pragma unroll
    for (int nt = 0; nt < 10; nt++) {
        const int col = nt * 8 + 2 * qd;
        uint2 oa, ob;
        oa.x = f2tf32(acc[nt][0] * invA); oa.y = f2tf32(acc[nt][1] * invA);
        ob.x = f2tf32(acc[nt][2] * invB); ob.y = f2tf32(acc[nt][3] * invB);
        *reinterpret_cast<uint2*>(&dA[col]) = oa;
        *reinterpret_cast<uint2*>(&dB[col]) = ob;
    }
}

// ---------------- launch ----------------
extern "C" void kernel_launch(void* const* d_in, const int* in_sizes, int n_in,
                              void* d_out, int out_size)
{
    const float* hidden = (const float*)d_in[0];
    const int*   cu     = (const int*)  d_in[1];
    const float* cosNK  = (const float*)d_in[2];
    const float* sinNK  = (const float*)d_in[3];
    const float* qkv_w  = (const float*)d_in[4];
    const float* qkv_b  = (const float*)d_in[5];
    const float* proj_w = (const float*)d_in[6];
    const float* proj_b = (const float*)d_in[7];
    float* out = (float*)d_out;

    float *qkv;
    uint32_t *hidtf, *qkvwtf, *projwtf, *qhib, *qlob, *khib, *klob, *vtf, *attntf;
    cudaGetSymbolAddress((void**)&hidtf,  g_hid_tf);
    cudaGetSymbolAddress((void**)&qkvwtf, g_qkvw_tf);
    cudaGetSymbolAddress((void**)&projwtf,g_projw_tf);
    cudaGetSymbolAddress((void**)&qkv,    g_qkv);
    cudaGetSymbolAddress((void**)&qhib,   g_qhib);
    cudaGetSymbolAddress((void**)&qlob,   g_qlob);
    cudaGetSymbolAddress((void**)&khib,   g_khib);
    cudaGetSymbolAddress((void**)&klob,   g_klob);
    cudaGetSymbolAddress((void**)&vtf,    g_vtf);
    cudaGetSymbolAddress((void**)&attntf, g_attn_tf);

    const size_t attn_smem = ATT_SMEM_WORDS * sizeof(uint32_t);
    static bool attr_done = false;
    if (!attr_done) {
        cudaFuncSetAttribute(tgemm128_kernel<3 * D, D>,
                             cudaFuncAttributeMaxDynamicSharedMemorySize, GEMM_SMEM1);
        cudaFuncSetAttribute(tgemm256_kernel<D, D>,
                             cudaFuncAttributeMaxDynamicSharedMemorySize, GEMM_SMEM2);
        cudaFuncSetAttribute(attn_mma_kernel,
                             cudaFuncAttributeMaxDynamicSharedMemorySize, (int)attn_smem);
        attr_done = true;
    }

    // 0) merged converts
    convert_all_kernel<<<(CVT_TOT + 255) / 256, 256>>>(
        hidden, qkv_w, proj_w, hidtf, qkvwtf, projwtf);

    // 1) QKV GEMM + bias
    tgemm128_kernel<3 * D, D><<<dim3((3 * D) / 128, N_TOK / 128), 256, GEMM_SMEM1>>>(
        hidtf, qkvwtf, qkv_b, qkv);

    // 2) RoPE + split (pair-owning, float2)
    rope_split_kernel<<<(N_TOK * H * HWPR + 255) / 256, 256>>>(
        qkv, cosNK, sinNK, qhib, qlob, khib, klob, vtf);

    // 3) attention (QTQ=64, KTK=64, fast path + rescale skip)
    attn_mma_kernel<<<dim3(N_TOK / QTQ, H), 128, attn_smem>>>(
        qhib, qlob, khib, klob, vtf, cu, attntf);

    // 4) projection GEMM + bias -> d_out
    tgemm256_kernel<D, D><<<dim3(D / 256, N_TOK / 128), 256, GEMM_SMEM2>>>(
        attntf, projwtf, proj_b, out);
}